// round 13
// baseline (speedup 1.0000x reference)
#include <cuda_runtime.h>
#include <cuda_bf16.h>
#include <cstdint>

// EngramGating via mma.sync (HMMA fallback on sm_103), R13 = R10 (71.7us) with
// shared B-fragment loads: each Whi load feeds both ehi- and elo-MMAs
// (bf16 3-term split ehi*Whi + ehi*Wlo + elo*Whi, fp32 accumulate).
// B LDS per 16-token tile: 240 -> 160 wavefronts.

#define HC       4
#define TILE_M   16
#define THREADS  256
#define NWARPS   8
#define NBLOCKS  296            // 148 SMs * 2 blocks

// ---- dynamic smem layout (bytes) ----
#define SB_STRIDE 164           // u64 per fragment-row (== 4 mod 16 -> conflict-free)
#define OFF_SB    0                               // 16 rows * 164 * 8 = 20992
#define OFF_BK    20992                           // 128 f
#define OFF_GG    21504                           // 128 f
#define OFF_BV    22016                           // 32 f
#define OFF_ES    22144                           // 8 warps * 16*40*4 = 20480
#define ES_W      2560
#define OFF_Q     (OFF_ES + NWARPS * ES_W)        // 42624
#define QW_BYTES  8704                            // 16 rows * 136 f * 4
#define OFF_GATE  (OFF_Q + NWARPS * QW_BYTES)     // 112256 ; 8 * 64 f
#define SMEM_TOTAL (OFF_GATE + NWARPS * 256)      // 114304

__device__ __forceinline__ unsigned su32(const void* p) {
    return (unsigned)__cvta_generic_to_shared(p);
}
__device__ __forceinline__ void cp16(unsigned d, const void* s) {
    asm volatile("cp.async.cg.shared.global [%0], [%1], 16;" :: "r"(d), "l"(s));
}
__device__ __forceinline__ unsigned packhi(float2 p) {
    __nv_bfloat162 h = __floats2bfloat162_rn(p.x, p.y);
    return *(unsigned*)&h;
}
__device__ __forceinline__ unsigned packlo(float2 p) {
    __nv_bfloat162 h = __floats2bfloat162_rn(p.x, p.y);
    float2 hf = __bfloat1622float2(h);
    __nv_bfloat162 l = __floats2bfloat162_rn(p.x - hf.x, p.y - hf.y);
    return *(unsigned*)&l;
}
__device__ __forceinline__ void mma_bf16(float4& d, const unsigned* a,
                                         unsigned b0, unsigned b1) {
    asm volatile(
        "mma.sync.aligned.m16n8k16.row.col.f32.bf16.bf16.f32 "
        "{%0,%1,%2,%3},{%4,%5,%6,%7},{%8,%9},{%0,%1,%2,%3};"
        : "+f"(d.x), "+f"(d.y), "+f"(d.z), "+f"(d.w)
        : "r"(a[0]), "r"(a[1]), "r"(a[2]), "r"(a[3]), "r"(b0), "r"(b1));
}

__global__ void __launch_bounds__(THREADS, 2)
engram_gating_mma(const float* __restrict__ emb,      // [T,32]
                  const float* __restrict__ hid,      // [T,4,32]
                  const float* __restrict__ Wv,       // [32,32]
                  const float* __restrict__ bv,       // [32]
                  const float* __restrict__ Wk,       // [4,32,32]
                  const float* __restrict__ bk,       // [4,32]
                  const float* __restrict__ g1,       // [4,32]
                  const float* __restrict__ g2,       // [4,32]
                  float* __restrict__ out,            // [T,4,32]
                  int nTok) {
    extern __shared__ __align__(16) char sm[];
    unsigned long long* sB = (unsigned long long*)(sm + OFF_SB);
    float* sBK = (float*)(sm + OFF_BK);
    float* sGG = (float*)(sm + OFF_GG);
    float* sBV = (float*)(sm + OFF_BV);

    const int tid = threadIdx.x;
    const int w = tid >> 5;
    const int lane = tid & 31;
    const int j = lane & 3;            // fragment quad-lane
    const int gID = lane >> 2;         // fragment group (0..7)
    const int r1 = gID, r2 = gID + 8;  // token rows covered by this thread

    // ---- weight prep: pre-packed bf16 fragment u64s ----
    // rr = (bt*2+kt)*4 + jj ; bt 0 = Whi, bt 1 = Wlo
    for (int i = tid; i < 2560; i += THREADS) {
        int n = i % 160, rr = i / 160;
        int jj = rr & 3, kt = (rr >> 2) & 1, bt = rr >> 3;
        int d0 = kt * 16 + 2 * jj;
        const float* wr = (n < 128) ? (Wk + n * 32) : (Wv + (n - 128) * 32);
        float2 pa = make_float2(wr[d0], wr[d0 + 1]);
        float2 pb = make_float2(wr[d0 + 8], wr[d0 + 9]);
        unsigned lo32, hi32;
        if (bt == 0) { lo32 = packhi(pa); hi32 = packhi(pb); }
        else         { lo32 = packlo(pa); hi32 = packlo(pb); }
        sB[rr * SB_STRIDE + n] = ((unsigned long long)hi32 << 32) | lo32;
    }
    for (int i = tid; i < 128; i += THREADS) {
        sBK[i] = bk[i];
        sGG[i] = g1[i] * g2[i];
    }
    if (tid < 32) sBV[tid] = bv[tid];
    __syncthreads();

    float* esf = (float*)(sm + OFF_ES) + w * 640;      // e stage, stride 40 f
    float* sQf = (float*)(sm + OFF_Q) + w * 2176;      // q stage, stride 136 f
    float* sGate = (float*)(sm + OFF_GATE) + w * 64;   // [r][h]
    const unsigned qA = su32(sQf);

    const int warpG = blockIdx.x * NWARPS + w;
    const int totW = NBLOCKS * NWARPS;
    const int nTiles = (nTok + TILE_M - 1) / TILE_M;

    const float EPS = 1.1920929e-07f;
    const float INV32 = 0.03125f;
    const float INVSQRT32 = 0.17677669529663687f;

    // ---- prologue: prefetch e for first tile ----
    float4 ep[4];
    if (warpG < nTiles) {
        int t0 = warpG * TILE_M;
#pragma unroll
        for (int it = 0; it < 4; it++) {
            int i = it * 32 + lane, r = i >> 3, c4 = i & 7;
            int row = min(t0 + r, nTok - 1);
            ep[it] = *(const float4*)(emb + (size_t)row * 32 + c4 * 4);
        }
    }

    for (int g = warpG; g < nTiles; g += totW) {
        const int t0 = g * TILE_M;

        // ---- 1. q -> smem via cp.async (16 x 16B per lane) ----
#pragma unroll
        for (int it = 0; it < 16; it++) {
            int i = it * 32 + lane, r = i >> 5, c = i & 31;
            int row = min(t0 + r, nTok - 1);
            cp16(qA + r * 544 + c * 16, hid + (size_t)row * 128 + c * 4);
        }
        asm volatile("cp.async.commit_group;");

        // ---- 2. e regs -> stage (zero pad rows) ----
#pragma unroll
        for (int it = 0; it < 4; it++) {
            int i = it * 32 + lane, r = i >> 3, c4 = i & 7;
            float4 v = (t0 + r < nTok) ? ep[it] : make_float4(0.f, 0.f, 0.f, 0.f);
            *(float4*)(esf + r * 40 + c4 * 4) = v;
        }
        __syncwarp();

        // ---- 3. A fragments (hi & lo) ----
        unsigned Ahi[2][4], Alo[2][4];
#pragma unroll
        for (int kt = 0; kt < 2; kt++) {
            int c0 = 16 * kt + 2 * j;
            float2 p0 = *(const float2*)(esf + r1 * 40 + c0);
            float2 p1 = *(const float2*)(esf + r2 * 40 + c0);
            float2 p2 = *(const float2*)(esf + r1 * 40 + c0 + 8);
            float2 p3 = *(const float2*)(esf + r2 * 40 + c0 + 8);
            Ahi[kt][0] = packhi(p0); Alo[kt][0] = packlo(p0);
            Ahi[kt][1] = packhi(p1); Alo[kt][1] = packlo(p1);
            Ahi[kt][2] = packhi(p2); Alo[kt][2] = packlo(p2);
            Ahi[kt][3] = packhi(p3); Alo[kt][3] = packlo(p3);
        }

        // ---- 4. prefetch e for next tile ----
        {
            int gn = g + totW;
            if (gn < nTiles) {
                int t0n = gn * TILE_M;
#pragma unroll
                for (int it = 0; it < 4; it++) {
                    int i = it * 32 + lane, r = i >> 3, c4 = i & 7;
                    int row = min(t0n + r, nTok - 1);
                    ep[it] = *(const float4*)(emb + (size_t)row * 32 + c4 * 4);
                }
            }
        }

        const unsigned long long* sBt = sB + (size_t)j * SB_STRIDE + gID;

        // ---- 5. value MMAs (n-tiles 16..19); Whi loads shared by ehi & elo ----
        float4 accV[4];
#pragma unroll
        for (int m = 0; m < 4; m++) accV[m] = make_float4(0.f, 0.f, 0.f, 0.f);
#pragma unroll
        for (int bt = 0; bt < 2; bt++)
#pragma unroll
            for (int kt = 0; kt < 2; kt++) {
                const unsigned long long* bp =
                    sBt + (bt * 8 + kt * 4) * SB_STRIDE + 128;
#pragma unroll
                for (int m = 0; m < 4; m++) {
                    unsigned long long b = bp[8 * m];
                    unsigned b0 = (unsigned)b, b1 = (unsigned)(b >> 32);
                    mma_bf16(accV[m], Ahi[kt], b0, b1);
                    if (bt == 0)               // Whi also pairs with elo
                        mma_bf16(accV[m], Alo[kt], b0, b1);
                }
            }

        // ---- 6. q ready ----
        asm volatile("cp.async.wait_group 0;");
        __syncwarp();

        // ---- 7. heads: key MMAs + gate epilogue (acc reuse) ----
#pragma unroll 1
        for (int h = 0; h < HC; h++) {
            float4 accK[4];
#pragma unroll
            for (int m = 0; m < 4; m++) accK[m] = make_float4(0.f, 0.f, 0.f, 0.f);
#pragma unroll
            for (int bt = 0; bt < 2; bt++)
#pragma unroll
                for (int kt = 0; kt < 2; kt++) {
                    const unsigned long long* bp =
                        sBt + (bt * 8 + kt * 4) * SB_STRIDE + 32 * h;
#pragma unroll
                    for (int m = 0; m < 4; m++) {
                        unsigned long long b = bp[8 * m];
                        unsigned b0 = (unsigned)b, b1 = (unsigned)(b >> 32);
                        mma_bf16(accK[m], Ahi[kt], b0, b1);
                        if (bt == 0)
                            mma_bf16(accK[m], Alo[kt], b0, b1);
                    }
                }

            const float* bkh = sBK + h * 32 + 2 * j;
            const float* ggh = sGG + h * 32 + 2 * j;
            const float* q1p = sQf + r1 * 136 + h * 32 + 2 * j;
            const float* q2p = sQf + r2 * 136 + h * 32 + 2 * j;

            float kk1 = 0.f, qq1 = 0.f, kq1 = 0.f;
            float kk2 = 0.f, qq2 = 0.f, kq2 = 0.f;
#pragma unroll
            for (int m = 0; m < 4; m++) {
                float2 bkp = *(const float2*)(bkh + 8 * m);
                float2 ggp = *(const float2*)(ggh + 8 * m);
                float2 q1 = *(const float2*)(q1p + 8 * m);
                float2 q2 = *(const float2*)(q2p + 8 * m);
                float k0 = accK[m].x + bkp.x, k1 = accK[m].y + bkp.y;   // row r1
                float k2 = accK[m].z + bkp.x, k3 = accK[m].w + bkp.y;   // row r2
                kk1 += k0 * k0 + k1 * k1;
                kk2 += k2 * k2 + k3 * k3;
                qq1 += q1.x * q1.x + q1.y * q1.y;
                qq2 += q2.x * q2.x + q2.y * q2.y;
                kq1 += k0 * ggp.x * q1.x + k1 * ggp.y * q1.y;
                kq2 += k2 * ggp.x * q2.x + k3 * ggp.y * q2.y;
            }
            // 2-step butterfly across the 4 j-lanes (serves 8 token-rows/instr)
#pragma unroll
            for (int msk = 1; msk < 4; msk <<= 1) {
                kk1 += __shfl_xor_sync(0xffffffffu, kk1, msk);
                qq1 += __shfl_xor_sync(0xffffffffu, qq1, msk);
                kq1 += __shfl_xor_sync(0xffffffffu, kq1, msk);
                kk2 += __shfl_xor_sync(0xffffffffu, kk2, msk);
                qq2 += __shfl_xor_sync(0xffffffffu, qq2, msk);
                kq2 += __shfl_xor_sync(0xffffffffu, kq2, msk);
            }
            float rA = kq1 * rsqrtf(fmaf(kk1, INV32, EPS))
                           * rsqrtf(fmaf(qq1, INV32, EPS)) * INVSQRT32;
            float rB = kq2 * rsqrtf(fmaf(kk2, INV32, EPS))
                           * rsqrtf(fmaf(qq2, INV32, EPS)) * INVSQRT32;
            float aA = sqrtf(fmaxf(fabsf(rA), 1e-6f));
            aA = (rA > 0.f) ? aA : ((rA < 0.f) ? -aA : 0.f);
            float aB = sqrtf(fmaxf(fabsf(rB), 1e-6f));
            aB = (rB > 0.f) ? aB : ((rB < 0.f) ? -aB : 0.f);
            float gA = 1.0f / (1.0f + __expf(-aA));
            float gB = 1.0f / (1.0f + __expf(-aB));
            if (j == 0) {
                sGate[r1 * 4 + h] = gA;
                sGate[r2 * 4 + h] = gB;
            }
        }
        __syncwarp();

        // ---- 8. value + gate stores ----
        {
            float4 gA = *(const float4*)&sGate[r1 * 4];   // gates h0..3, row r1
            float4 gB = *(const float4*)&sGate[r2 * 4];
            const bool okA = (t0 + r1) < nTok;
            const bool okB = (t0 + r2) < nTok;
            float* oA = out + (size_t)(t0 + r1) * 128 + 2 * j;
            float* oB = out + (size_t)(t0 + r2) * 128 + 2 * j;
            const float gAh[4] = {gA.x, gA.y, gA.z, gA.w};
            const float gBh[4] = {gB.x, gB.y, gB.z, gB.w};
#pragma unroll
            for (int m = 0; m < 4; m++) {
                float2 bvp = *(const float2*)(sBV + 8 * m + 2 * j);
                float v0 = accV[m].x + bvp.x, v1 = accV[m].y + bvp.y;  // r1
                float v2 = accV[m].z + bvp.x, v3 = accV[m].w + bvp.y;  // r2
#pragma unroll
                for (int h = 0; h < 4; h++) {
                    if (okA)
                        *(float2*)(oA + h * 32 + 8 * m) =
                            make_float2(gAh[h] * v0, gAh[h] * v1);
                    if (okB)
                        *(float2*)(oB + h * 32 + 8 * m) =
                            make_float2(gBh[h] * v2, gBh[h] * v3);
                }
            }
        }
        __syncwarp();
    }
}

extern "C" void kernel_launch(void* const* d_in, const int* in_sizes, int n_in,
                              void* d_out, int out_size) {
    const float* emb = (const float*)d_in[0];
    const float* hid = (const float*)d_in[1];
    const float* Wv  = (const float*)d_in[2];
    const float* bv  = (const float*)d_in[3];
    const float* Wk  = (const float*)d_in[4];
    const float* bk  = (const float*)d_in[5];
    const float* g1  = (const float*)d_in[6];
    const float* g2  = (const float*)d_in[7];
    float* out = (float*)d_out;

    int nTok = in_sizes[0] / 32;

    cudaFuncSetAttribute(engram_gating_mma,
                         cudaFuncAttributeMaxDynamicSharedMemorySize, SMEM_TOTAL);

    engram_gating_mma<<<NBLOCKS, THREADS, SMEM_TOTAL>>>(
        emb, hid, Wv, bv, Wk, bk, g1, g2, out, nTok);
}

// round 14
// speedup vs baseline: 1.5564x; 1.5564x over previous
#include <cuda_runtime.h>
#include <cuda_bf16.h>
#include <cstdint>

// EngramGating via mma.sync (HMMA fallback on sm_103), R14 = R10 (71.7us) +
//  (1) batched-m Whi sharing: load 4 B frags, 4x mma(Ahi), 4x mma(Alo)
//      (dependent MMAs 4 apart; B LDS/tile 120 -> 80)
//  (2) e staged via single-buffer cp.async issued one iteration ahead
//      (frees the 16-reg ep[] prefetch that pays for the batched b regs)
//  (3) clamp-free fast path for full tiles.

#define HC       4
#define TILE_M   16
#define THREADS  256
#define NWARPS   8
#define NBLOCKS  296            // 148 SMs * 2 blocks

// ---- dynamic smem layout (bytes) ----
#define SB_STRIDE 164           // u64 per fragment-row (== 4 mod 16 -> conflict-free)
#define OFF_SB    0                               // 16 rows * 164 * 8 = 20992
#define OFF_BK    20992                           // 128 f
#define OFF_GG    21504                           // 128 f
#define OFF_BV    22016                           // 32 f
#define OFF_ES    22144                           // 8 warps * 16*40*4 = 20480
#define ES_W      2560
#define OFF_Q     (OFF_ES + NWARPS * ES_W)        // 42624
#define QW_BYTES  8704                            // 16 rows * 136 f * 4
#define OFF_GATE  (OFF_Q + NWARPS * QW_BYTES)     // 112256 ; 8 * 64 f
#define SMEM_TOTAL (OFF_GATE + NWARPS * 256)      // 114304

__device__ __forceinline__ unsigned su32(const void* p) {
    return (unsigned)__cvta_generic_to_shared(p);
}
__device__ __forceinline__ void cp16(unsigned d, const void* s) {
    asm volatile("cp.async.cg.shared.global [%0], [%1], 16;" :: "r"(d), "l"(s));
}
#define CP_COMMIT() asm volatile("cp.async.commit_group;")
#define CP_WAIT1()  asm volatile("cp.async.wait_group 1;")

__device__ __forceinline__ unsigned packhi(float2 p) {
    __nv_bfloat162 h = __floats2bfloat162_rn(p.x, p.y);
    return *(unsigned*)&h;
}
__device__ __forceinline__ unsigned packlo(float2 p) {
    __nv_bfloat162 h = __floats2bfloat162_rn(p.x, p.y);
    float2 hf = __bfloat1622float2(h);
    __nv_bfloat162 l = __floats2bfloat162_rn(p.x - hf.x, p.y - hf.y);
    return *(unsigned*)&l;
}
__device__ __forceinline__ void mma_bf16(float4& d, const unsigned* a,
                                         unsigned b0, unsigned b1) {
    asm volatile(
        "mma.sync.aligned.m16n8k16.row.col.f32.bf16.bf16.f32 "
        "{%0,%1,%2,%3},{%4,%5,%6,%7},{%8,%9},{%0,%1,%2,%3};"
        : "+f"(d.x), "+f"(d.y), "+f"(d.z), "+f"(d.w)
        : "r"(a[0]), "r"(a[1]), "r"(a[2]), "r"(a[3]), "r"(b0), "r"(b1));
}

__global__ void __launch_bounds__(THREADS, 2)
engram_gating_mma(const float* __restrict__ emb,      // [T,32]
                  const float* __restrict__ hid,      // [T,4,32]
                  const float* __restrict__ Wv,       // [32,32]
                  const float* __restrict__ bv,       // [32]
                  const float* __restrict__ Wk,       // [4,32,32]
                  const float* __restrict__ bk,       // [4,32]
                  const float* __restrict__ g1,       // [4,32]
                  const float* __restrict__ g2,       // [4,32]
                  float* __restrict__ out,            // [T,4,32]
                  int nTok) {
    extern __shared__ __align__(16) char sm[];
    unsigned long long* sB = (unsigned long long*)(sm + OFF_SB);
    float* sBK = (float*)(sm + OFF_BK);
    float* sGG = (float*)(sm + OFF_GG);
    float* sBV = (float*)(sm + OFF_BV);

    const int tid = threadIdx.x;
    const int w = tid >> 5;
    const int lane = tid & 31;
    const int j = lane & 3;            // fragment quad-lane
    const int gID = lane >> 2;         // fragment group (0..7)
    const int r1 = gID, r2 = gID + 8;  // token rows covered by this thread

    // ---- weight prep: pre-packed bf16 fragment u64s ----
    // rr = (bt*2+kt)*4 + jj ; bt 0 = Whi, bt 1 = Wlo
    for (int i = tid; i < 2560; i += THREADS) {
        int n = i % 160, rr = i / 160;
        int jj = rr & 3, kt = (rr >> 2) & 1, bt = rr >> 3;
        int d0 = kt * 16 + 2 * jj;
        const float* wr = (n < 128) ? (Wk + n * 32) : (Wv + (n - 128) * 32);
        float2 pa = make_float2(wr[d0], wr[d0 + 1]);
        float2 pb = make_float2(wr[d0 + 8], wr[d0 + 9]);
        unsigned lo32, hi32;
        if (bt == 0) { lo32 = packhi(pa); hi32 = packhi(pb); }
        else         { lo32 = packlo(pa); hi32 = packlo(pb); }
        sB[rr * SB_STRIDE + n] = ((unsigned long long)hi32 << 32) | lo32;
    }
    for (int i = tid; i < 128; i += THREADS) {
        sBK[i] = bk[i];
        sGG[i] = g1[i] * g2[i];
    }
    if (tid < 32) sBV[tid] = bv[tid];
    __syncthreads();

    float* esf = (float*)(sm + OFF_ES) + w * 640;      // e stage, stride 40 f
    float* sQf = (float*)(sm + OFF_Q) + w * 2176;      // q stage, stride 136 f
    float* sGate = (float*)(sm + OFF_GATE) + w * 64;   // [r][h]
    const unsigned qA = su32(sQf);
    const unsigned eA = su32(esf);

    const int warpG = blockIdx.x * NWARPS + w;
    const int totW = NBLOCKS * NWARPS;
    const int nTiles = (nTok + TILE_M - 1) / TILE_M;

    const float EPS = 1.1920929e-07f;
    const float INV32 = 0.03125f;
    const float INVSQRT32 = 0.17677669529663687f;

    // e issue: 4 x cp16 per lane (chunk f = it*32+lane -> row f>>3, col4 f&7)
    auto issue_e = [&](int g) {
        const int t0 = g * TILE_M;
        if (t0 + TILE_M <= nTok) {
            const char* ebase = (const char*)(emb + (size_t)t0 * 32);
#pragma unroll
            for (int it = 0; it < 4; it++) {
                int f = it * 32 + lane;
                cp16(eA + (f >> 3) * 160 + (f & 7) * 16, ebase + f * 16);
            }
        } else {
#pragma unroll
            for (int it = 0; it < 4; it++) {
                int f = it * 32 + lane;
                int row = min(t0 + (f >> 3), nTok - 1);
                cp16(eA + (f >> 3) * 160 + (f & 7) * 16,
                     (const char*)(emb + (size_t)row * 32 + (f & 7) * 4));
            }
        }
    };

    // ---- prologue: stage e for first tile (group E0) ----
    if (warpG < nTiles) issue_e(warpG);
    CP_COMMIT();

    for (int g = warpG; g < nTiles; g += totW) {
        const int t0 = g * TILE_M;
        const bool full = (t0 + TILE_M) <= nTok;

        // ---- 1. q -> smem via cp.async (16 rows x 512B) ; pending {E_g,Q_g} ----
        if (full) {
            const char* hbase = (const char*)(hid + (size_t)t0 * 128);
#pragma unroll
            for (int it = 0; it < 16; it++)
                cp16(qA + it * 544 + lane * 16, hbase + it * 512 + lane * 4 * 4);
        } else {
#pragma unroll
            for (int it = 0; it < 16; it++) {
                int row = min(t0 + it, nTok - 1);
                cp16(qA + it * 544 + lane * 16,
                     (const char*)(hid + (size_t)row * 128 + lane * 4));
            }
        }
        CP_COMMIT();

        // ---- 2. wait for e (oldest group) ----
        CP_WAIT1();

        // ---- 3. A fragments (hi & lo) from e stage ----
        unsigned Ahi[2][4], Alo[2][4];
#pragma unroll
        for (int kt = 0; kt < 2; kt++) {
            int c0 = 16 * kt + 2 * j;
            float2 p0 = *(const float2*)(esf + r1 * 40 + c0);
            float2 p1 = *(const float2*)(esf + r2 * 40 + c0);
            float2 p2 = *(const float2*)(esf + r1 * 40 + c0 + 8);
            float2 p3 = *(const float2*)(esf + r2 * 40 + c0 + 8);
            Ahi[kt][0] = packhi(p0); Alo[kt][0] = packlo(p0);
            Ahi[kt][1] = packhi(p1); Alo[kt][1] = packlo(p1);
            Ahi[kt][2] = packhi(p2); Alo[kt][2] = packlo(p2);
            Ahi[kt][3] = packhi(p3); Alo[kt][3] = packlo(p3);
        }
        // zero pad rows for tail tiles (mask A instead of smem)
        if (!full) {
#pragma unroll
            for (int kt = 0; kt < 2; kt++) {
                if (t0 + r1 >= nTok) { Ahi[kt][0] = Alo[kt][0] = 0u;
                                       Ahi[kt][2] = Alo[kt][2] = 0u; }
                if (t0 + r2 >= nTok) { Ahi[kt][1] = Alo[kt][1] = 0u;
                                       Ahi[kt][3] = Alo[kt][3] = 0u; }
            }
        }

        // ---- 4. stage e for NEXT tile (stage free now) ; pending {Q_g,E_next} ----
        {
            int gn = g + totW;
            if (gn < nTiles) issue_e(gn);
            CP_COMMIT();
        }

        const unsigned long long* sBt = sB + (size_t)j * SB_STRIDE + gID;

        // ---- 5. value MMAs: batched-m, Whi shared by Ahi & Alo ----
        float4 accV[4];
#pragma unroll
        for (int m = 0; m < 4; m++) accV[m] = make_float4(0.f, 0.f, 0.f, 0.f);
#pragma unroll
        for (int kt = 0; kt < 2; kt++) {           // bt = 0 (Whi)
            const unsigned long long* bp = sBt + (kt * 4) * SB_STRIDE + 128;
            unsigned long long b0 = bp[0], b1 = bp[8], b2 = bp[16], b3 = bp[24];
            mma_bf16(accV[0], Ahi[kt], (unsigned)b0, (unsigned)(b0 >> 32));
            mma_bf16(accV[1], Ahi[kt], (unsigned)b1, (unsigned)(b1 >> 32));
            mma_bf16(accV[2], Ahi[kt], (unsigned)b2, (unsigned)(b2 >> 32));
            mma_bf16(accV[3], Ahi[kt], (unsigned)b3, (unsigned)(b3 >> 32));
            mma_bf16(accV[0], Alo[kt], (unsigned)b0, (unsigned)(b0 >> 32));
            mma_bf16(accV[1], Alo[kt], (unsigned)b1, (unsigned)(b1 >> 32));
            mma_bf16(accV[2], Alo[kt], (unsigned)b2, (unsigned)(b2 >> 32));
            mma_bf16(accV[3], Alo[kt], (unsigned)b3, (unsigned)(b3 >> 32));
        }
#pragma unroll
        for (int kt = 0; kt < 2; kt++) {           // bt = 1 (Wlo) x Ahi
            const unsigned long long* bp = sBt + (8 + kt * 4) * SB_STRIDE + 128;
            unsigned long long b0 = bp[0], b1 = bp[8], b2 = bp[16], b3 = bp[24];
            mma_bf16(accV[0], Ahi[kt], (unsigned)b0, (unsigned)(b0 >> 32));
            mma_bf16(accV[1], Ahi[kt], (unsigned)b1, (unsigned)(b1 >> 32));
            mma_bf16(accV[2], Ahi[kt], (unsigned)b2, (unsigned)(b2 >> 32));
            mma_bf16(accV[3], Ahi[kt], (unsigned)b3, (unsigned)(b3 >> 32));
        }

        // ---- 6. q ready (E_next stays pending) ----
        CP_WAIT1();

        // ---- 7. heads: key MMAs + gate epilogue ----
#pragma unroll 1
        for (int h = 0; h < HC; h++) {
            float4 accK[4];
#pragma unroll
            for (int m = 0; m < 4; m++) accK[m] = make_float4(0.f, 0.f, 0.f, 0.f);
#pragma unroll
            for (int kt = 0; kt < 2; kt++) {       // Whi shared
                const unsigned long long* bp = sBt + (kt * 4) * SB_STRIDE + 32 * h;
                unsigned long long b0 = bp[0], b1 = bp[8], b2 = bp[16], b3 = bp[24];
                mma_bf16(accK[0], Ahi[kt], (unsigned)b0, (unsigned)(b0 >> 32));
                mma_bf16(accK[1], Ahi[kt], (unsigned)b1, (unsigned)(b1 >> 32));
                mma_bf16(accK[2], Ahi[kt], (unsigned)b2, (unsigned)(b2 >> 32));
                mma_bf16(accK[3], Ahi[kt], (unsigned)b3, (unsigned)(b3 >> 32));
                mma_bf16(accK[0], Alo[kt], (unsigned)b0, (unsigned)(b0 >> 32));
                mma_bf16(accK[1], Alo[kt], (unsigned)b1, (unsigned)(b1 >> 32));
                mma_bf16(accK[2], Alo[kt], (unsigned)b2, (unsigned)(b2 >> 32));
                mma_bf16(accK[3], Alo[kt], (unsigned)b3, (unsigned)(b3 >> 32));
            }
#pragma unroll
            for (int kt = 0; kt < 2; kt++) {       // Wlo x Ahi
                const unsigned long long* bp =
                    sBt + (8 + kt * 4) * SB_STRIDE + 32 * h;
                unsigned long long b0 = bp[0], b1 = bp[8], b2 = bp[16], b3 = bp[24];
                mma_bf16(accK[0], Ahi[kt], (unsigned)b0, (unsigned)(b0 >> 32));
                mma_bf16(accK[1], Ahi[kt], (unsigned)b1, (unsigned)(b1 >> 32));
                mma_bf16(accK[2], Ahi[kt], (unsigned)b2, (unsigned)(b2 >> 32));
                mma_bf16(accK[3], Ahi[kt], (unsigned)b3, (unsigned)(b3 >> 32));
            }

            const float* bkh = sBK + h * 32 + 2 * j;
            const float* ggh = sGG + h * 32 + 2 * j;
            const float* q1p = sQf + r1 * 136 + h * 32 + 2 * j;
            const float* q2p = sQf + r2 * 136 + h * 32 + 2 * j;

            float kk1 = 0.f, qq1 = 0.f, kq1 = 0.f;
            float kk2 = 0.f, qq2 = 0.f, kq2 = 0.f;
#pragma unroll
            for (int m = 0; m < 4; m++) {
                float2 bkp = *(const float2*)(bkh + 8 * m);
                float2 ggp = *(const float2*)(ggh + 8 * m);
                float2 q1 = *(const float2*)(q1p + 8 * m);
                float2 q2 = *(const float2*)(q2p + 8 * m);
                float k0 = accK[m].x + bkp.x, k1 = accK[m].y + bkp.y;   // row r1
                float k2 = accK[m].z + bkp.x, k3 = accK[m].w + bkp.y;   // row r2
                kk1 += k0 * k0 + k1 * k1;
                kk2 += k2 * k2 + k3 * k3;
                qq1 += q1.x * q1.x + q1.y * q1.y;
                qq2 += q2.x * q2.x + q2.y * q2.y;
                kq1 += k0 * ggp.x * q1.x + k1 * ggp.y * q1.y;
                kq2 += k2 * ggp.x * q2.x + k3 * ggp.y * q2.y;
            }
            // 2-step butterfly across the 4 j-lanes (serves 8 token-rows/instr)
#pragma unroll
            for (int msk = 1; msk < 4; msk <<= 1) {
                kk1 += __shfl_xor_sync(0xffffffffu, kk1, msk);
                qq1 += __shfl_xor_sync(0xffffffffu, qq1, msk);
                kq1 += __shfl_xor_sync(0xffffffffu, kq1, msk);
                kk2 += __shfl_xor_sync(0xffffffffu, kk2, msk);
                qq2 += __shfl_xor_sync(0xffffffffu, qq2, msk);
                kq2 += __shfl_xor_sync(0xffffffffu, kq2, msk);
            }
            float rA = kq1 * rsqrtf(fmaf(kk1, INV32, EPS))
                           * rsqrtf(fmaf(qq1, INV32, EPS)) * INVSQRT32;
            float rB = kq2 * rsqrtf(fmaf(kk2, INV32, EPS))
                           * rsqrtf(fmaf(qq2, INV32, EPS)) * INVSQRT32;
            float aA = sqrtf(fmaxf(fabsf(rA), 1e-6f));
            aA = (rA > 0.f) ? aA : ((rA < 0.f) ? -aA : 0.f);
            float aB = sqrtf(fmaxf(fabsf(rB), 1e-6f));
            aB = (rB > 0.f) ? aB : ((rB < 0.f) ? -aB : 0.f);
            float gA = 1.0f / (1.0f + __expf(-aA));
            float gB = 1.0f / (1.0f + __expf(-aB));
            if (j == 0) {
                sGate[r1 * 4 + h] = gA;
                sGate[r2 * 4 + h] = gB;
            }
        }
        __syncwarp();

        // ---- 8. value + gate stores ----
        {
            float4 gA = *(const float4*)&sGate[r1 * 4];   // gates h0..3, row r1
            float4 gB = *(const float4*)&sGate[r2 * 4];
            const bool okA = full || (t0 + r1) < nTok;
            const bool okB = full || (t0 + r2) < nTok;
            float* oA = out + (size_t)(t0 + r1) * 128 + 2 * j;
            float* oB = out + (size_t)(t0 + r2) * 128 + 2 * j;
            const float gAh[4] = {gA.x, gA.y, gA.z, gA.w};
            const float gBh[4] = {gB.x, gB.y, gB.z, gB.w};
#pragma unroll
            for (int m = 0; m < 4; m++) {
                float2 bvp = *(const float2*)(sBV + 8 * m + 2 * j);
                float v0 = accV[m].x + bvp.x, v1 = accV[m].y + bvp.y;  // r1
                float v2 = accV[m].z + bvp.x, v3 = accV[m].w + bvp.y;  // r2
#pragma unroll
                for (int h = 0; h < 4; h++) {
                    if (okA)
                        *(float2*)(oA + h * 32 + 8 * m) =
                            make_float2(gAh[h] * v0, gAh[h] * v1);
                    if (okB)
                        *(float2*)(oB + h * 32 + 8 * m) =
                            make_float2(gBh[h] * v2, gBh[h] * v3);
                }
            }
        }
        __syncwarp();
    }
}

extern "C" void kernel_launch(void* const* d_in, const int* in_sizes, int n_in,
                              void* d_out, int out_size) {
    const float* emb = (const float*)d_in[0];
    const float* hid = (const float*)d_in[1];
    const float* Wv  = (const float*)d_in[2];
    const float* bv  = (const float*)d_in[3];
    const float* Wk  = (const float*)d_in[4];
    const float* bk  = (const float*)d_in[5];
    const float* g1  = (const float*)d_in[6];
    const float* g2  = (const float*)d_in[7];
    float* out = (float*)d_out;

    int nTok = in_sizes[0] / 32;

    cudaFuncSetAttribute(engram_gating_mma,
                         cudaFuncAttributeMaxDynamicSharedMemorySize, SMEM_TOTAL);

    engram_gating_mma<<<NBLOCKS, THREADS, SMEM_TOTAL>>>(
        emb, hid, Wv, bv, Wk, bk, g1, g2, out, nTok);
}

// round 16
// speedup vs baseline: 1.6281x; 1.0461x over previous
#include <cuda_runtime.h>
#include <cuda_bf16.h>
#include <cstdint>

// EngramGating via mma.sync (HMMA fallback on sm_103), R15 = R14 (68.3us) +
// coalesced output: values staged into the dead q buffer (stride 36), store
// phase remapped to one STG.128 of 512B-contiguous output per row.
// Output store wavefronts per tile: ~256 -> ~112.

#define HC       4
#define TILE_M   16
#define THREADS  256
#define NWARPS   8
#define NBLOCKS  296            // 148 SMs * 2 blocks

// ---- dynamic smem layout (bytes) ----
#define SB_STRIDE 164           // u64 per fragment-row (== 4 mod 16 -> conflict-free)
#define OFF_SB    0                               // 16 rows * 164 * 8 = 20992
#define OFF_BK    20992                           // 128 f
#define OFF_GG    21504                           // 128 f
#define OFF_BV    22016                           // 32 f
#define OFF_ES    22144                           // 8 warps * 16*40*4 = 20480
#define ES_W      2560
#define OFF_Q     (OFF_ES + NWARPS * ES_W)        // 42624
#define QW_BYTES  8704                            // 16 rows * 136 f * 4
#define OFF_GATE  (OFF_Q + NWARPS * QW_BYTES)     // 112256 ; 8 * 64 f
#define SMEM_TOTAL (OFF_GATE + NWARPS * 256)      // 114304

__device__ __forceinline__ unsigned su32(const void* p) {
    return (unsigned)__cvta_generic_to_shared(p);
}
__device__ __forceinline__ void cp16(unsigned d, const void* s) {
    asm volatile("cp.async.cg.shared.global [%0], [%1], 16;" :: "r"(d), "l"(s));
}
#define CP_COMMIT() asm volatile("cp.async.commit_group;")
#define CP_WAIT1()  asm volatile("cp.async.wait_group 1;")

__device__ __forceinline__ unsigned packhi(float2 p) {
    __nv_bfloat162 h = __floats2bfloat162_rn(p.x, p.y);
    return *(unsigned*)&h;
}
__device__ __forceinline__ unsigned packlo(float2 p) {
    __nv_bfloat162 h = __floats2bfloat162_rn(p.x, p.y);
    float2 hf = __bfloat1622float2(h);
    __nv_bfloat162 l = __floats2bfloat162_rn(p.x - hf.x, p.y - hf.y);
    return *(unsigned*)&l;
}
__device__ __forceinline__ void mma_bf16(float4& d, const unsigned* a,
                                         unsigned b0, unsigned b1) {
    asm volatile(
        "mma.sync.aligned.m16n8k16.row.col.f32.bf16.bf16.f32 "
        "{%0,%1,%2,%3},{%4,%5,%6,%7},{%8,%9},{%0,%1,%2,%3};"
        : "+f"(d.x), "+f"(d.y), "+f"(d.z), "+f"(d.w)
        : "r"(a[0]), "r"(a[1]), "r"(a[2]), "r"(a[3]), "r"(b0), "r"(b1));
}

__global__ void __launch_bounds__(THREADS, 2)
engram_gating_mma(const float* __restrict__ emb,      // [T,32]
                  const float* __restrict__ hid,      // [T,4,32]
                  const float* __restrict__ Wv,       // [32,32]
                  const float* __restrict__ bv,       // [32]
                  const float* __restrict__ Wk,       // [4,32,32]
                  const float* __restrict__ bk,       // [4,32]
                  const float* __restrict__ g1,       // [4,32]
                  const float* __restrict__ g2,       // [4,32]
                  float* __restrict__ out,            // [T,4,32]
                  int nTok) {
    extern __shared__ __align__(16) char sm[];
    unsigned long long* sB = (unsigned long long*)(sm + OFF_SB);
    float* sBK = (float*)(sm + OFF_BK);
    float* sGG = (float*)(sm + OFF_GG);
    float* sBV = (float*)(sm + OFF_BV);

    const int tid = threadIdx.x;
    const int w = tid >> 5;
    const int lane = tid & 31;
    const int j = lane & 3;            // fragment quad-lane
    const int gID = lane >> 2;         // fragment group (0..7)
    const int r1 = gID, r2 = gID + 8;  // token rows covered by this thread

    // ---- weight prep: pre-packed bf16 fragment u64s ----
    // rr = (bt*2+kt)*4 + jj ; bt 0 = Whi, bt 1 = Wlo
    for (int i = tid; i < 2560; i += THREADS) {
        int n = i % 160, rr = i / 160;
        int jj = rr & 3, kt = (rr >> 2) & 1, bt = rr >> 3;
        int d0 = kt * 16 + 2 * jj;
        const float* wr = (n < 128) ? (Wk + n * 32) : (Wv + (n - 128) * 32);
        float2 pa = make_float2(wr[d0], wr[d0 + 1]);
        float2 pb = make_float2(wr[d0 + 8], wr[d0 + 9]);
        unsigned lo32, hi32;
        if (bt == 0) { lo32 = packhi(pa); hi32 = packhi(pb); }
        else         { lo32 = packlo(pa); hi32 = packlo(pb); }
        sB[rr * SB_STRIDE + n] = ((unsigned long long)hi32 << 32) | lo32;
    }
    for (int i = tid; i < 128; i += THREADS) {
        sBK[i] = bk[i];
        sGG[i] = g1[i] * g2[i];
    }
    if (tid < 32) sBV[tid] = bv[tid];
    __syncthreads();

    float* esf = (float*)(sm + OFF_ES) + w * 640;      // e stage, stride 40 f
    float* sQf = (float*)(sm + OFF_Q) + w * 2176;      // q stage, stride 136 f
    float* sV  = sQf;                                  // value stage (q dead), stride 36 f
    float* sGate = (float*)(sm + OFF_GATE) + w * 64;   // [r][h]
    const unsigned qA = su32(sQf);
    const unsigned eA = su32(esf);

    const int warpG = blockIdx.x * NWARPS + w;
    const int totW = NBLOCKS * NWARPS;
    const int nTiles = (nTok + TILE_M - 1) / TILE_M;

    const float EPS = 1.1920929e-07f;
    const float INV32 = 0.03125f;
    const float INVSQRT32 = 0.17677669529663687f;

    // e issue: 4 x cp16 per lane (chunk f = it*32+lane -> row f>>3, col4 f&7)
    auto issue_e = [&](int g) {
        const int t0 = g * TILE_M;
        if (t0 + TILE_M <= nTok) {
            const char* ebase = (const char*)(emb + (size_t)t0 * 32);
#pragma unroll
            for (int it = 0; it < 4; it++) {
                int f = it * 32 + lane;
                cp16(eA + (f >> 3) * 160 + (f & 7) * 16, ebase + f * 16);
            }
        } else {
#pragma unroll
            for (int it = 0; it < 4; it++) {
                int f = it * 32 + lane;
                int row = min(t0 + (f >> 3), nTok - 1);
                cp16(eA + (f >> 3) * 160 + (f & 7) * 16,
                     (const char*)(emb + (size_t)row * 32 + (f & 7) * 4));
            }
        }
    };

    // ---- prologue: stage e for first tile (group E0) ----
    if (warpG < nTiles) issue_e(warpG);
    CP_COMMIT();

    for (int g = warpG; g < nTiles; g += totW) {
        const int t0 = g * TILE_M;
        const bool full = (t0 + TILE_M) <= nTok;

        // ---- 1. q -> smem via cp.async (16 rows x 512B) ; pending {E_g,Q_g} ----
        if (full) {
            const char* hbase = (const char*)(hid + (size_t)t0 * 128);
#pragma unroll
            for (int it = 0; it < 16; it++)
                cp16(qA + it * 544 + lane * 16, hbase + it * 512 + lane * 4 * 4);
        } else {
#pragma unroll
            for (int it = 0; it < 16; it++) {
                int row = min(t0 + it, nTok - 1);
                cp16(qA + it * 544 + lane * 16,
                     (const char*)(hid + (size_t)row * 128 + lane * 4));
            }
        }
        CP_COMMIT();

        // ---- 2. wait for e (oldest group) ----
        CP_WAIT1();

        // ---- 3. A fragments (hi & lo) from e stage ----
        unsigned Ahi[2][4], Alo[2][4];
#pragma unroll
        for (int kt = 0; kt < 2; kt++) {
            int c0 = 16 * kt + 2 * j;
            float2 p0 = *(const float2*)(esf + r1 * 40 + c0);
            float2 p1 = *(const float2*)(esf + r2 * 40 + c0);
            float2 p2 = *(const float2*)(esf + r1 * 40 + c0 + 8);
            float2 p3 = *(const float2*)(esf + r2 * 40 + c0 + 8);
            Ahi[kt][0] = packhi(p0); Alo[kt][0] = packlo(p0);
            Ahi[kt][1] = packhi(p1); Alo[kt][1] = packlo(p1);
            Ahi[kt][2] = packhi(p2); Alo[kt][2] = packlo(p2);
            Ahi[kt][3] = packhi(p3); Alo[kt][3] = packlo(p3);
        }
        // zero pad rows for tail tiles (mask A instead of smem)
        if (!full) {
#pragma unroll
            for (int kt = 0; kt < 2; kt++) {
                if (t0 + r1 >= nTok) { Ahi[kt][0] = Alo[kt][0] = 0u;
                                       Ahi[kt][2] = Alo[kt][2] = 0u; }
                if (t0 + r2 >= nTok) { Ahi[kt][1] = Alo[kt][1] = 0u;
                                       Ahi[kt][3] = Alo[kt][3] = 0u; }
            }
        }

        // ---- 4. stage e for NEXT tile (stage free now) ; pending {Q_g,E_next} ----
        {
            int gn = g + totW;
            if (gn < nTiles) issue_e(gn);
            CP_COMMIT();
        }

        const unsigned long long* sBt = sB + (size_t)j * SB_STRIDE + gID;

        // ---- 5. value MMAs: batched-m, Whi shared by Ahi & Alo ----
        float4 accV[4];
#pragma unroll
        for (int m = 0; m < 4; m++) accV[m] = make_float4(0.f, 0.f, 0.f, 0.f);
#pragma unroll
        for (int kt = 0; kt < 2; kt++) {           // bt = 0 (Whi)
            const unsigned long long* bp = sBt + (kt * 4) * SB_STRIDE + 128;
            unsigned long long b0 = bp[0], b1 = bp[8], b2 = bp[16], b3 = bp[24];
            mma_bf16(accV[0], Ahi[kt], (unsigned)b0, (unsigned)(b0 >> 32));
            mma_bf16(accV[1], Ahi[kt], (unsigned)b1, (unsigned)(b1 >> 32));
            mma_bf16(accV[2], Ahi[kt], (unsigned)b2, (unsigned)(b2 >> 32));
            mma_bf16(accV[3], Ahi[kt], (unsigned)b3, (unsigned)(b3 >> 32));
            mma_bf16(accV[0], Alo[kt], (unsigned)b0, (unsigned)(b0 >> 32));
            mma_bf16(accV[1], Alo[kt], (unsigned)b1, (unsigned)(b1 >> 32));
            mma_bf16(accV[2], Alo[kt], (unsigned)b2, (unsigned)(b2 >> 32));
            mma_bf16(accV[3], Alo[kt], (unsigned)b3, (unsigned)(b3 >> 32));
        }
#pragma unroll
        for (int kt = 0; kt < 2; kt++) {           // bt = 1 (Wlo) x Ahi
            const unsigned long long* bp = sBt + (8 + kt * 4) * SB_STRIDE + 128;
            unsigned long long b0 = bp[0], b1 = bp[8], b2 = bp[16], b3 = bp[24];
            mma_bf16(accV[0], Ahi[kt], (unsigned)b0, (unsigned)(b0 >> 32));
            mma_bf16(accV[1], Ahi[kt], (unsigned)b1, (unsigned)(b1 >> 32));
            mma_bf16(accV[2], Ahi[kt], (unsigned)b2, (unsigned)(b2 >> 32));
            mma_bf16(accV[3], Ahi[kt], (unsigned)b3, (unsigned)(b3 >> 32));
        }

        // ---- 6. q ready (E_next stays pending) ----
        CP_WAIT1();

        // ---- 7. heads: key MMAs + gate epilogue ----
#pragma unroll 1
        for (int h = 0; h < HC; h++) {
            float4 accK[4];
#pragma unroll
            for (int m = 0; m < 4; m++) accK[m] = make_float4(0.f, 0.f, 0.f, 0.f);
#pragma unroll
            for (int kt = 0; kt < 2; kt++) {       // Whi shared
                const unsigned long long* bp = sBt + (kt * 4) * SB_STRIDE + 32 * h;
                unsigned long long b0 = bp[0], b1 = bp[8], b2 = bp[16], b3 = bp[24];
                mma_bf16(accK[0], Ahi[kt], (unsigned)b0, (unsigned)(b0 >> 32));
                mma_bf16(accK[1], Ahi[kt], (unsigned)b1, (unsigned)(b1 >> 32));
                mma_bf16(accK[2], Ahi[kt], (unsigned)b2, (unsigned)(b2 >> 32));
                mma_bf16(accK[3], Ahi[kt], (unsigned)b3, (unsigned)(b3 >> 32));
                mma_bf16(accK[0], Alo[kt], (unsigned)b0, (unsigned)(b0 >> 32));
                mma_bf16(accK[1], Alo[kt], (unsigned)b1, (unsigned)(b1 >> 32));
                mma_bf16(accK[2], Alo[kt], (unsigned)b2, (unsigned)(b2 >> 32));
                mma_bf16(accK[3], Alo[kt], (unsigned)b3, (unsigned)(b3 >> 32));
            }
#pragma unroll
            for (int kt = 0; kt < 2; kt++) {       // Wlo x Ahi
                const unsigned long long* bp =
                    sBt + (8 + kt * 4) * SB_STRIDE + 32 * h;
                unsigned long long b0 = bp[0], b1 = bp[8], b2 = bp[16], b3 = bp[24];
                mma_bf16(accK[0], Ahi[kt], (unsigned)b0, (unsigned)(b0 >> 32));
                mma_bf16(accK[1], Ahi[kt], (unsigned)b1, (unsigned)(b1 >> 32));
                mma_bf16(accK[2], Ahi[kt], (unsigned)b2, (unsigned)(b2 >> 32));
                mma_bf16(accK[3], Ahi[kt], (unsigned)b3, (unsigned)(b3 >> 32));
            }

            const float* bkh = sBK + h * 32 + 2 * j;
            const float* ggh = sGG + h * 32 + 2 * j;
            const float* q1p = sQf + r1 * 136 + h * 32 + 2 * j;
            const float* q2p = sQf + r2 * 136 + h * 32 + 2 * j;

            float kk1 = 0.f, qq1 = 0.f, kq1 = 0.f;
            float kk2 = 0.f, qq2 = 0.f, kq2 = 0.f;
#pragma unroll
            for (int m = 0; m < 4; m++) {
                float2 bkp = *(const float2*)(bkh + 8 * m);
                float2 ggp = *(const float2*)(ggh + 8 * m);
                float2 q1 = *(const float2*)(q1p + 8 * m);
                float2 q2 = *(const float2*)(q2p + 8 * m);
                float k0 = accK[m].x + bkp.x, k1 = accK[m].y + bkp.y;   // row r1
                float k2 = accK[m].z + bkp.x, k3 = accK[m].w + bkp.y;   // row r2
                kk1 += k0 * k0 + k1 * k1;
                kk2 += k2 * k2 + k3 * k3;
                qq1 += q1.x * q1.x + q1.y * q1.y;
                qq2 += q2.x * q2.x + q2.y * q2.y;
                kq1 += k0 * ggp.x * q1.x + k1 * ggp.y * q1.y;
                kq2 += k2 * ggp.x * q2.x + k3 * ggp.y * q2.y;
            }
            // 2-step butterfly across the 4 j-lanes (serves 8 token-rows/instr)
#pragma unroll
            for (int msk = 1; msk < 4; msk <<= 1) {
                kk1 += __shfl_xor_sync(0xffffffffu, kk1, msk);
                qq1 += __shfl_xor_sync(0xffffffffu, qq1, msk);
                kq1 += __shfl_xor_sync(0xffffffffu, kq1, msk);
                kk2 += __shfl_xor_sync(0xffffffffu, kk2, msk);
                qq2 += __shfl_xor_sync(0xffffffffu, qq2, msk);
                kq2 += __shfl_xor_sync(0xffffffffu, kq2, msk);
            }
            float rA = kq1 * rsqrtf(fmaf(kk1, INV32, EPS))
                           * rsqrtf(fmaf(qq1, INV32, EPS)) * INVSQRT32;
            float rB = kq2 * rsqrtf(fmaf(kk2, INV32, EPS))
                           * rsqrtf(fmaf(qq2, INV32, EPS)) * INVSQRT32;
            float aA = sqrtf(fmaxf(fabsf(rA), 1e-6f));
            aA = (rA > 0.f) ? aA : ((rA < 0.f) ? -aA : 0.f);
            float aB = sqrtf(fmaxf(fabsf(rB), 1e-6f));
            aB = (rB > 0.f) ? aB : ((rB < 0.f) ? -aB : 0.f);
            float gA = 1.0f / (1.0f + __expf(-aA));
            float gB = 1.0f / (1.0f + __expf(-aB));
            if (j == 0) {
                sGate[r1 * 4 + h] = gA;
                sGate[r2 * 4 + h] = gB;
            }
        }
        __syncwarp();

        // ---- 8. stage values (q buffer dead; stride 36 f), then coalesced out ----
        {
#pragma unroll
            for (int m = 0; m < 4; m++) {
                float2 bvp = *(const float2*)(sBV + 8 * m + 2 * j);
                *(float2*)(sV + r1 * 36 + 8 * m + 2 * j) =
                    make_float2(accV[m].x + bvp.x, accV[m].y + bvp.y);
                *(float2*)(sV + r2 * 36 + 8 * m + 2 * j) =
                    make_float2(accV[m].z + bvp.x, accV[m].w + bvp.y);
            }
        }
        __syncwarp();
        {
            const int hL = lane >> 3;          // head of this lane's out chunk
            const int k4 = lane & 7;           // 4-float span within head
#pragma unroll
            for (int it = 0; it < TILE_M; it++) {
                if (full || (t0 + it) < nTok) {
                    float4 v = *(const float4*)(sV + it * 36 + k4 * 4);
                    float gt = sGate[it * 4 + hL];
                    *(float4*)(out + (size_t)(t0 + it) * 128 + lane * 4) =
                        make_float4(gt * v.x, gt * v.y, gt * v.z, gt * v.w);
                }
            }
        }
        __syncwarp();
    }
}

extern "C" void kernel_launch(void* const* d_in, const int* in_sizes, int n_in,
                              void* d_out, int out_size) {
    const float* emb = (const float*)d_in[0];
    const float* hid = (const float*)d_in[1];
    const float* Wv  = (const float*)d_in[2];
    const float* bv  = (const float*)d_in[3];
    const float* Wk  = (const float*)d_in[4];
    const float* bk  = (const float*)d_in[5];
    const float* g1  = (const float*)d_in[6];
    const float* g2  = (const float*)d_in[7];
    float* out = (float*)d_out;

    int nTok = in_sizes[0] / 32;

    cudaFuncSetAttribute(engram_gating_mma,
                         cudaFuncAttributeMaxDynamicSharedMemorySize, SMEM_TOTAL);

    engram_gating_mma<<<NBLOCKS, THREADS, SMEM_TOTAL>>>(
        emb, hid, Wv, bv, Wk, bk, g1, g2, out, nTok);
}